// round 1
// baseline (speedup 1.0000x reference)
#include <cuda_runtime.h>

#define D      128
#define NQ     512
#define NREF   100000
#define KNN    10
#define BQ     128          // queries per block tile
#define BN     128          // refs per smem chunk
#define NSPLIT 72           // ref splits (grid.x)
#define CHUNK  1408         // refs per split = 11 chunks of 128 (72*1408 = 101376 >= 100000)
#define SD_STRIDE 129       // dist buffer row stride (odd -> conflict-free column scans)

#define SF_FLOATS (128 * 128)
#define SR_FLOATS (128 * 128)
#define SD_FLOATS (128 * SD_STRIDE)
#define SMEM_BYTES ((SF_FLOATS + SR_FLOATS + SD_FLOATS) * 4)

#define BIGF 3.0e37f

// ---------------------------------------------------------------- scratch
__device__ float g_x2[NQ];
__device__ float g_y2[NREF];
__device__ float g_cand[NSPLIT * KNN * NQ];   // [split*KNN + o][q] transposed for coalescing

// ---------------------------------------------------------------- helpers
__device__ __forceinline__ unsigned long long pk2(float v) {
    unsigned u = __float_as_uint(v);
    unsigned long long r;
    asm("mov.b64 %0, {%1, %2};" : "=l"(r) : "r"(u), "r"(u));
    return r;
}
__device__ __forceinline__ void fma2(unsigned long long& d, unsigned long long a, unsigned long long b) {
    // packed 2x fp32 FMA -- doubles fp32 throughput vs FFMA-3reg on sm_10x
    asm("fma.rn.f32x2 %0, %1, %2, %0;" : "+l"(d) : "l"(a), "l"(b));
}
__device__ __forceinline__ float f2lo(unsigned long long v) { return __uint_as_float((unsigned)v); }
__device__ __forceinline__ float f2hi(unsigned long long v) { return __uint_as_float((unsigned)(v >> 32)); }

__device__ __forceinline__ void topk_insert(float (&tk)[KNN], float v) {
    if (v < tk[KNN - 1]) {
        tk[KNN - 1] = v;
        #pragma unroll
        for (int j = KNN - 1; j > 0; --j) {
            float lo = fminf(tk[j - 1], tk[j]);
            float hi = fmaxf(tk[j - 1], tk[j]);
            tk[j - 1] = lo;
            tk[j]     = hi;
        }
    }
}

// Load a 128x128 fp32 tile, transposing to k-major with a XOR swizzle so that
// both the transpose stores AND the GEMM LDS.128 reads are bank-conflict-free.
// Logical element (k, c) lives at float index  k*128 + ((((c>>2) ^ ((k>>2)&7))<<2) | (c&3)).
// Rows >= rows_valid are zero-filled.
__device__ __forceinline__ void load_tile_T(float* __restrict__ dst,
                                            const float* __restrict__ src,
                                            int rows_valid) {
    const int t = threadIdx.x;
    const int w = t >> 5, l = t & 31;
    #pragma unroll
    for (int gi = 0; gi < 4; ++gi) {
        const int grp = w * 4 + gi;           // 0..31 row groups of 4
        const int row = grp * 4 + (l & 3);    // tile column (query/ref index)
        const bool ok = row < rows_valid;
        const float4* s = (const float4*)(src + (size_t)row * D);
        #pragma unroll
        for (int seg = 0; seg < 4; ++seg) {
            const int c4 = (l >> 2) + seg * 8;   // 0..31 float4 chunk along k
            float4 v = ok ? s[c4] : make_float4(0.f, 0.f, 0.f, 0.f);
            const int k0 = c4 * 4;
            #pragma unroll
            for (int j = 0; j < 4; ++j) {
                const int k = k0 + j;
                const int idx = k * 128 + ((((row >> 2) ^ ((k >> 2) & 7)) << 2) | (row & 3));
                dst[idx] = (&v.x)[j];
            }
        }
    }
}

// ---------------------------------------------------------------- kernel 1: norms
__global__ void norms_kernel(const float* __restrict__ feat, const float* __restrict__ refs) {
    int row = blockIdx.x * 8 + (threadIdx.x >> 5);
    int l = threadIdx.x & 31;
    const float* src;
    float* dst;
    if (row < NREF) {
        src = refs + (size_t)row * D;
        dst = g_y2 + row;
    } else {
        int r = row - NREF;
        if (r >= NQ) return;
        src = feat + (size_t)r * D;
        dst = g_x2 + r;
    }
    float4 v = ((const float4*)src)[l];
    float s = v.x * v.x + v.y * v.y + v.z * v.z + v.w * v.w;
    #pragma unroll
    for (int o = 16; o; o >>= 1) s += __shfl_xor_sync(0xffffffffu, s, o);
    if (l == 0) *dst = s;
}

// ---------------------------------------------------------------- kernel 2: fused dist + top-k
__global__ void __launch_bounds__(256, 1)
knn_main_kernel(const float* __restrict__ feat, const float* __restrict__ refs) {
    extern __shared__ float smem[];
    float* sf = smem;                        // feat tile, k-major swizzled [128][128]
    float* sr = smem + SF_FLOATS;            // ref  tile, k-major swizzled [128][128]
    float* sd = sr + SR_FLOATS;              // d^2 tile [128][SD_STRIDE]

    const int t = threadIdx.x;
    const int w = t >> 5, l = t & 31;
    const int wm = w & 3, wn = w >> 2;       // warp grid 4(m) x 2(n)
    const int lm = l & 3, ln = l >> 2;       // lane grid 4(m) x 8(n)
    const int M0 = wm * 32 + lm * 8;         // thread m-range: M0..M0+7
    const int n0 = wn * 64 + ln * 4;         // thread n-range: n0..n0+3 and n0+32..n0+35
    const int ca0 = M0 >> 2;                 // float4 column for a-loads (even)
    const int cb0 = n0 >> 2;                 // float4 column for b-loads

    const int split = blockIdx.x;
    const int qbase = blockIdx.y * BQ;

    load_tile_T(sf, feat + (size_t)qbase * D, 128);

    float xq[8];
    #pragma unroll
    for (int i = 0; i < 8; ++i) xq[i] = g_x2[qbase + M0 + i];

    float tk[KNN];
    #pragma unroll
    for (int j = 0; j < KNN; ++j) tk[j] = BIGF;

    __syncthreads();

    const int sbase = split * CHUNK;
    for (int ch = 0; ch < CHUNK / BN; ++ch) {
        const int cbase = sbase + ch * BN;
        if (cbase >= NREF) break;
        int valid = NREF - cbase;
        if (valid > BN) valid = BN;

        load_tile_T(sr, refs + (size_t)cbase * D, valid);
        __syncthreads();

        unsigned long long acc[4][8];
        #pragma unroll
        for (int i = 0; i < 4; ++i)
            #pragma unroll
            for (int j = 0; j < 8; ++j) acc[i][j] = 0ull;

        const ulonglong2* sfu = (const ulonglong2*)sf;
        const float4*     sru = (const float4*)sr;

        #pragma unroll 4
        for (int k = 0; k < D; ++k) {
            const int g  = (k >> 2) & 7;
            const int kb = k << 5;                       // k*32 in 16B units
            ulonglong2 Aa = sfu[kb + (ca0 ^ g)];         // m pairs (M0,M0+1),(M0+2,M0+3)
            ulonglong2 Ab = sfu[kb + ((ca0 + 1) ^ g)];   // (M0+4,M0+5),(M0+6,M0+7)
            float4 B0 = sru[kb + (cb0 ^ g)];             // n0..n0+3
            float4 B1 = sru[kb + ((cb0 + 8) ^ g)];       // n0+32..n0+35

            unsigned long long a2[4] = {Aa.x, Aa.y, Ab.x, Ab.y};
            unsigned long long bb[8];
            bb[0] = pk2(B0.x); bb[1] = pk2(B0.y); bb[2] = pk2(B0.z); bb[3] = pk2(B0.w);
            bb[4] = pk2(B1.x); bb[5] = pk2(B1.y); bb[6] = pk2(B1.z); bb[7] = pk2(B1.w);

            #pragma unroll
            for (int i = 0; i < 4; ++i)
                #pragma unroll
                for (int j = 0; j < 8; ++j) fma2(acc[i][j], a2[i], bb[j]);
        }

        // epilogue: d^2 = x^2 + y^2 - 2*dot -> sd
        float yv[8];
        #pragma unroll
        for (int j = 0; j < 8; ++j) {
            const int n = n0 + ((j < 4) ? j : (28 + j));
            const int r = cbase + n;
            yv[j] = (r < NREF) ? g_y2[r] : BIGF;
        }
        #pragma unroll
        for (int i = 0; i < 4; ++i) {
            #pragma unroll
            for (int j = 0; j < 8; ++j) {
                const int n = n0 + ((j < 4) ? j : (28 + j));
                const float dlo = fmaf(-2.f, f2lo(acc[i][j]), xq[2 * i]     + yv[j]);
                const float dhi = fmaf(-2.f, f2hi(acc[i][j]), xq[2 * i + 1] + yv[j]);
                sd[(M0 + 2 * i)     * SD_STRIDE + n] = dlo;
                sd[(M0 + 2 * i + 1) * SD_STRIDE + n] = dhi;
            }
        }
        __syncthreads();

        // selection: 2 selector threads per query, each scans 64 columns
        {
            const int q = t & 127, s = t >> 7;
            const float* rowp = sd + q * SD_STRIDE + s * 64;
            #pragma unroll 4
            for (int c = 0; c < 64; ++c) topk_insert(tk, rowp[c]);
        }
        __syncthreads();
    }

    // merge the two selectors' sorted lists per query via smem staging
    __syncthreads();
    {
        const int q = t & 127, s = t >> 7;
        #pragma unroll
        for (int j = 0; j < KNN; ++j) sd[(s * KNN + j) * 128 + q] = tk[j];
    }
    __syncthreads();
    if (t < 128) {
        float out[KNN];
        int ia = 0, ib = 0;
        #pragma unroll
        for (int o = 0; o < KNN; ++o) {
            const float va = sd[ia * 128 + t];
            const float vb = sd[(KNN + ib) * 128 + t];
            const bool ta = va <= vb;
            out[o] = ta ? va : vb;
            ia += ta;
            ib += !ta;
        }
        const int qg = qbase + t;
        #pragma unroll
        for (int o = 0; o < KNN; ++o)
            g_cand[(split * KNN + o) * NQ + qg] = out[o];
    }
}

// ---------------------------------------------------------------- kernel 3: finalize
__global__ void finalize_kernel(float* __restrict__ out) {
    const int q = blockIdx.x * blockDim.x + threadIdx.x;
    if (q >= NQ) return;
    float tk[KNN];
    #pragma unroll
    for (int j = 0; j < KNN; ++j) tk[j] = BIGF;
    #pragma unroll 4
    for (int i = 0; i < NSPLIT * KNN; ++i) {
        topk_insert(tk, g_cand[i * NQ + q]);
    }
    float s = 0.f;
    #pragma unroll
    for (int j = 0; j < KNN; ++j) s += sqrtf(fmaxf(tk[j], 0.f));
    out[q] = -s * (1.0f / KNN);
}

// ---------------------------------------------------------------- launch
extern "C" void kernel_launch(void* const* d_in, const int* in_sizes, int n_in,
                              void* d_out, int out_size) {
    const float* feat = (const float*)d_in[0];
    const float* refs = (const float*)d_in[1];
    if (n_in >= 2 && in_sizes[0] > in_sizes[1]) {  // defensive: feat is the small one
        feat = (const float*)d_in[1];
        refs = (const float*)d_in[0];
    }

    cudaFuncSetAttribute(knn_main_kernel,
                         cudaFuncAttributeMaxDynamicSharedMemorySize, SMEM_BYTES);

    norms_kernel<<<(NREF + NQ) / 8, 256>>>(feat, refs);

    dim3 grid(NSPLIT, NQ / BQ);
    knn_main_kernel<<<grid, 256, SMEM_BYTES>>>(feat, refs);

    finalize_kernel<<<2, 256>>>((float*)d_out);
}

// round 3
// speedup vs baseline: 2.0488x; 2.0488x over previous
#include <cuda_runtime.h>
#include <cstdint>

#define D      128
#define NQ     512
#define NREF   100000
#define KNN    10
#define NSPLIT 36
#define NCH    22            // 36*22*128 = 101376 >= 100000
#define BN     128
#define SA     132           // A/B tile row stride (floats): banks (4*gr + lc) conflict-free
#define SDS    129           // dist buffer row stride
#define AF     (128 * SA)    // floats per A/B tile
#define SDF    (128 * SDS)
#define SMEM_BYTES ((2 * AF + SDF) * 4)

#define BIGF 3.0e37f

// ---------------------------------------------------------------- scratch
__device__ float g_x2[NQ];
__device__ float g_y2[NREF];
__device__ float g_cand[NSPLIT * KNN * NQ];

// ---------------------------------------------------------------- helpers
__device__ __forceinline__ uint32_t smem_u32(const void* p) {
    uint32_t a;
    asm("{ .reg .u64 t; cvta.to.shared.u64 t, %1; cvt.u32.u64 %0, t; }" : "=r"(a) : "l"(p));
    return a;
}
__device__ __forceinline__ void cpa16(uint32_t dst, const void* src, int bytes) {
    asm volatile("cp.async.cg.shared.global [%0], [%1], 16, %2;"
                 :: "r"(dst), "l"(src), "r"(bytes) : "memory");
}
#define CPA_COMMIT() asm volatile("cp.async.commit_group;" ::: "memory")
#define CPA_WAIT0()  asm volatile("cp.async.wait_group 0;" ::: "memory")

__device__ __forceinline__ void mma_tf32(float& c0, float& c1, float& c2, float& c3,
                                         uint32_t a0, uint32_t a1, uint32_t a2, uint32_t a3,
                                         uint32_t b0, uint32_t b1) {
    asm volatile("mma.sync.aligned.m16n8k8.row.col.f32.tf32.tf32.f32 "
                 "{%0,%1,%2,%3}, {%4,%5,%6,%7}, {%8,%9}, {%0,%1,%2,%3};"
                 : "+f"(c0), "+f"(c1), "+f"(c2), "+f"(c3)
                 : "r"(a0), "r"(a1), "r"(a2), "r"(a3), "r"(b0), "r"(b1));
}

__device__ __forceinline__ void topk_insert(float (&tk)[KNN], float v) {
    if (v < tk[KNN - 1]) {
        tk[KNN - 1] = v;
        #pragma unroll
        for (int j = KNN - 1; j > 0; --j) {
            float lo = fminf(tk[j - 1], tk[j]);
            float hi = fmaxf(tk[j - 1], tk[j]);
            tk[j - 1] = lo;
            tk[j]     = hi;
        }
    }
}

// Load a 128-row x 128-col fp32 tile into smem [row][k], row stride SA floats.
// Rows >= glimit are zero-filled (cp.async src-size 0).
__device__ __forceinline__ void load_tile(uint32_t dst, const float* __restrict__ src,
                                          int gbase, int glimit) {
    const int t = threadIdx.x;
    const int f4 = t & 31;          // 16B chunk along k (0..31)
    const int rb = t >> 5;          // row base (0..7)
    #pragma unroll
    for (int i = 0; i < 16; ++i) {
        const int row = rb + i * 8;
        const int gr = gbase + row;
        const int ok = (gr < glimit) ? 16 : 0;
        const int gc = (gr < glimit) ? gr : (glimit - 1);
        const float* s = src + (size_t)gc * D + f4 * 4;
        cpa16(dst + (uint32_t)(row * SA + f4 * 4) * 4u, s, ok);
    }
}

// ---------------------------------------------------------------- kernel 1: norms
__global__ void __launch_bounds__(256)
norms_kernel(const float* __restrict__ feat, const float* __restrict__ refs) {
    const int w = threadIdx.x >> 5, l = threadIdx.x & 31;
    const int base_row = (blockIdx.x * 8 + w) * 4;
    const float* srcp;
    float* dst;
    if (base_row < NREF) { srcp = refs + (size_t)base_row * D; dst = g_y2 + base_row; }
    else {
        int r = base_row - NREF;
        if (r >= NQ) return;
        srcp = feat + (size_t)r * D; dst = g_x2 + r;
    }
    const float4* s4 = (const float4*)srcp;
    float4 v0 = s4[l], v1 = s4[l + 32], v2 = s4[l + 64], v3 = s4[l + 96];
    float s0 = v0.x * v0.x + v0.y * v0.y + v0.z * v0.z + v0.w * v0.w;
    float s1 = v1.x * v1.x + v1.y * v1.y + v1.z * v1.z + v1.w * v1.w;
    float s2 = v2.x * v2.x + v2.y * v2.y + v2.z * v2.z + v2.w * v2.w;
    float s3 = v3.x * v3.x + v3.y * v3.y + v3.z * v3.z + v3.w * v3.w;
    #pragma unroll
    for (int o = 16; o; o >>= 1) {
        s0 += __shfl_xor_sync(0xffffffffu, s0, o);
        s1 += __shfl_xor_sync(0xffffffffu, s1, o);
        s2 += __shfl_xor_sync(0xffffffffu, s2, o);
        s3 += __shfl_xor_sync(0xffffffffu, s3, o);
    }
    if (l == 0) *(float4*)dst = make_float4(s0, s1, s2, s3);
}

// ---------------------------------------------------------------- kernel 2: mma.sync tf32 main
__global__ void __launch_bounds__(256, 1)
knn_main_kernel(const float* __restrict__ feat, const float* __restrict__ refs) {
    extern __shared__ __align__(16) float smem[];
    float* sA = smem;            // [128][SA] queries, row-major [m][k]
    float* sB = smem + AF;       // [128][SA] refs,    row-major [n][k]
    float* sD = smem + 2 * AF;   // [128][SDS] d^2 buffer

    const uint32_t sAu = smem_u32(sA), sBu = smem_u32(sB);

    const int t  = threadIdx.x;
    const int w  = t >> 5, l = t & 31;
    const int wm = w >> 2, wn = w & 3;     // warp grid 2(m) x 4(n)
    const int gr = l >> 2, lc = l & 3;     // fragment lane coords

    const int split = blockIdx.x;
    const int qbase = blockIdx.y * 128;
    const int sbase = split * NCH * BN;

    // prologue: A tile + chunk0 B tile
    load_tile(sAu, feat, qbase, qbase + 128);
    load_tile(sBu, refs, sbase, NREF);
    CPA_COMMIT();

    float tk[KNN];
    #pragma unroll
    for (int j = 0; j < KNN; ++j) tk[j] = BIGF;

    for (int ch = 0; ch < NCH; ++ch) {
        const int cbase = sbase + ch * BN;

        // y2 for this thread's 8 output columns (latency hidden under k-loop)
        float y2r[8];
        #pragma unroll
        for (int j = 0; j < 4; ++j) {
            const int c0 = wn * 32 + j * 8 + 2 * lc;
            const int n0 = cbase + c0;
            y2r[2 * j]     = (n0     < NREF) ? g_y2[n0]     : BIGF;
            y2r[2 * j + 1] = (n0 + 1 < NREF) ? g_y2[n0 + 1] : BIGF;
        }

        CPA_WAIT0();
        __syncthreads();      // B resident; previous selection done reading sD

        float acc[4][4][4];
        #pragma unroll
        for (int i = 0; i < 4; ++i)
            #pragma unroll
            for (int j = 0; j < 4; ++j)
                #pragma unroll
                for (int e = 0; e < 4; ++e) acc[i][j][e] = 0.f;

        #pragma unroll
        for (int ks = 0; ks < 16; ++ks) {
            const int kc = ks * 8 + lc;
            uint32_t af[4][4], bf[4][2];
            #pragma unroll
            for (int i = 0; i < 4; ++i) {
                const float* p = sA + (wm * 64 + i * 16 + gr) * SA + kc;
                af[i][0] = __float_as_uint(p[0]);
                af[i][1] = __float_as_uint(p[8 * SA]);
                af[i][2] = __float_as_uint(p[4]);
                af[i][3] = __float_as_uint(p[8 * SA + 4]);
            }
            #pragma unroll
            for (int j = 0; j < 4; ++j) {
                const float* p = sB + (wn * 32 + j * 8 + gr) * SA + kc;
                bf[j][0] = __float_as_uint(p[0]);
                bf[j][1] = __float_as_uint(p[4]);
            }
            #pragma unroll
            for (int i = 0; i < 4; ++i)
                #pragma unroll
                for (int j = 0; j < 4; ++j)
                    mma_tf32(acc[i][j][0], acc[i][j][1], acc[i][j][2], acc[i][j][3],
                             af[i][0], af[i][1], af[i][2], af[i][3],
                             bf[j][0], bf[j][1]);
        }

        __syncthreads();      // all warps done reading sB

        // prefetch next chunk's B (overlaps epilogue + selection)
        if (ch + 1 < NCH) load_tile(sBu, refs, cbase + BN, NREF);
        CPA_COMMIT();

        // epilogue: d^2' = y^2 - 2*dot -> sD
        #pragma unroll
        for (int i = 0; i < 4; ++i) {
            const int r0 = wm * 64 + i * 16 + gr;
            #pragma unroll
            for (int j = 0; j < 4; ++j) {
                const int c0 = wn * 32 + j * 8 + 2 * lc;
                sD[r0 * SDS + c0]           = fmaf(-2.f, acc[i][j][0], y2r[2 * j]);
                sD[r0 * SDS + c0 + 1]       = fmaf(-2.f, acc[i][j][1], y2r[2 * j + 1]);
                sD[(r0 + 8) * SDS + c0]     = fmaf(-2.f, acc[i][j][2], y2r[2 * j]);
                sD[(r0 + 8) * SDS + c0 + 1] = fmaf(-2.f, acc[i][j][3], y2r[2 * j + 1]);
            }
        }
        __syncthreads();

        // selection: 2 threads per query, 64 columns each
        {
            const int q = t & 127, s = t >> 7;
            const float* rowp = sD + q * SDS + s * 64;
            #pragma unroll 4
            for (int c = 0; c < 64; ++c) topk_insert(tk, rowp[c]);
        }
    }

    // merge the two selectors' sorted lists per query via sD staging
    __syncthreads();
    {
        const int q = t & 127, s = t >> 7;
        #pragma unroll
        for (int j = 0; j < KNN; ++j) sD[(s * KNN + j) * 128 + q] = tk[j];
    }
    __syncthreads();
    if (t < 128) {
        float out[KNN];
        int ia = 0, ib = 0;
        #pragma unroll
        for (int o = 0; o < KNN; ++o) {
            const float va = sD[ia * 128 + t];
            const float vb = sD[(KNN + ib) * 128 + t];
            const bool ta = va <= vb;
            out[o] = ta ? va : vb;
            ia += ta;
            ib += !ta;
        }
        const int qg = qbase + t;
        #pragma unroll
        for (int o = 0; o < KNN; ++o)
            g_cand[(split * KNN + o) * NQ + qg] = out[o];
    }
}

// ---------------------------------------------------------------- kernel 3: finalize
__global__ void finalize_kernel(float* __restrict__ out) {
    const int q = blockIdx.x * blockDim.x + threadIdx.x;
    if (q >= NQ) return;
    float tk[KNN];
    #pragma unroll
    for (int j = 0; j < KNN; ++j) tk[j] = BIGF;
    #pragma unroll 4
    for (int i = 0; i < NSPLIT * KNN; ++i)
        topk_insert(tk, g_cand[i * NQ + q]);
    const float x2 = g_x2[q];
    float s = 0.f;
    #pragma unroll
    for (int j = 0; j < KNN; ++j) s += sqrtf(fmaxf(x2 + tk[j], 0.f));
    out[q] = -s * (1.0f / KNN);
}

// ---------------------------------------------------------------- launch
extern "C" void kernel_launch(void* const* d_in, const int* in_sizes, int n_in,
                              void* d_out, int out_size) {
    const float* feat = (const float*)d_in[0];
    const float* refs = (const float*)d_in[1];
    if (n_in >= 2 && in_sizes[0] > in_sizes[1]) {
        feat = (const float*)d_in[1];
        refs = (const float*)d_in[0];
    }

    cudaFuncSetAttribute(knn_main_kernel,
                         cudaFuncAttributeMaxDynamicSharedMemorySize, SMEM_BYTES);

    norms_kernel<<<(NREF + NQ) / 32, 256>>>(feat, refs);

    dim3 grid(NSPLIT, NQ / 128);
    knn_main_kernel<<<grid, 256, SMEM_BYTES>>>(feat, refs);

    finalize_kernel<<<2, 256>>>((float*)d_out);
}

// round 4
// speedup vs baseline: 2.5100x; 1.2251x over previous
#include <cuda_runtime.h>
#include <cuda_bf16.h>
#include <cstdint>

#define D      128
#define NQ     512
#define NREF   100000
#define KNN    10
#define NSPLIT 36
#define NCH    22            // 36*22*128 = 101376 >= 100000
#define BN     128
#define ROWB   272           // smem tile row stride in bytes (136 bf16, 17x16B)
#define TILEB  (128 * ROWB)  // 34816 B per bf16 tile
#define SDS    129           // dist buffer row stride (floats)
#define SDF    (128 * SDS)
#define SMEM_BYTES (3 * TILEB + SDF * 4)   // A + 2xB + dist = 170496

#define BIGF 3.0e37f

// ---------------------------------------------------------------- scratch
__device__ float g_x2[NQ];
__device__ float g_y2[NREF];
__device__ float g_cand[NSPLIT * KNN * NQ];
__device__ __nv_bfloat16 g_feat_bf[NQ * D];
__device__ __nv_bfloat16 g_refs_bf[NREF * D];

// ---------------------------------------------------------------- helpers
__device__ __forceinline__ uint32_t smem_u32(const void* p) {
    uint32_t a;
    asm("{ .reg .u64 t; cvta.to.shared.u64 t, %1; cvt.u32.u64 %0, t; }" : "=r"(a) : "l"(p));
    return a;
}
__device__ __forceinline__ void cpa16(uint32_t dst, const void* src, int bytes) {
    asm volatile("cp.async.cg.shared.global [%0], [%1], 16, %2;"
                 :: "r"(dst), "l"(src), "r"(bytes) : "memory");
}
#define CPA_COMMIT() asm volatile("cp.async.commit_group;" ::: "memory")
#define CPA_WAIT0()  asm volatile("cp.async.wait_group 0;" ::: "memory")

#define LDSM4(r, a)                                                            \
    asm volatile("ldmatrix.sync.aligned.m8n8.x4.shared.b16 {%0,%1,%2,%3}, [%4];" \
                 : "=r"((r)[0]), "=r"((r)[1]), "=r"((r)[2]), "=r"((r)[3])      \
                 : "r"(a))

__device__ __forceinline__ void mma_bf16(float* c, const uint32_t* a,
                                         uint32_t b0, uint32_t b1) {
    asm volatile("mma.sync.aligned.m16n8k16.row.col.f32.bf16.bf16.f32 "
                 "{%0,%1,%2,%3}, {%4,%5,%6,%7}, {%8,%9}, {%0,%1,%2,%3};"
                 : "+f"(c[0]), "+f"(c[1]), "+f"(c[2]), "+f"(c[3])
                 : "r"(a[0]), "r"(a[1]), "r"(a[2]), "r"(a[3]), "r"(b0), "r"(b1));
}

__device__ __forceinline__ void topk_insert(float (&tk)[KNN], float v) {
    if (v < tk[KNN - 1]) {
        tk[KNN - 1] = v;
        #pragma unroll
        for (int j = KNN - 1; j > 0; --j) {
            float lo = fminf(tk[j - 1], tk[j]);
            float hi = fmaxf(tk[j - 1], tk[j]);
            tk[j - 1] = lo;
            tk[j]     = hi;
        }
    }
}

// Load a 128-row x 128-col bf16 tile into smem [row][k], row stride ROWB bytes.
// 8 cp.async of 16B per thread. Rows >= glimit zero-filled.
__device__ __forceinline__ void load_tile_bf(uint32_t dst, const __nv_bfloat16* __restrict__ src,
                                             int gbase, int glimit) {
    const int t = threadIdx.x;
    const int c = t & 15;           // 16B chunk along k (0..15)
    const int rb = t >> 4;          // row base (0..15)
    #pragma unroll
    for (int i = 0; i < 8; ++i) {
        const int row = rb + i * 16;
        const int gr = gbase + row;
        const int ok = (gr < glimit) ? 16 : 0;
        const int gc = (gr < glimit) ? gr : (glimit - 1);
        const __nv_bfloat16* s = src + (size_t)gc * D + c * 8;
        cpa16(dst + (uint32_t)(row * ROWB + c * 16), s, ok);
    }
}

// ---------------------------------------------------------------- kernel 1: norms + bf16 convert
__global__ void __launch_bounds__(256)
norms_kernel(const float* __restrict__ feat, const float* __restrict__ refs) {
    const int w = threadIdx.x >> 5, l = threadIdx.x & 31;
    const int base_row = (blockIdx.x * 8 + w) * 4;
    const float* srcp;
    float* dst;
    __nv_bfloat16* bdst;
    if (base_row < NREF) {
        srcp = refs + (size_t)base_row * D; dst = g_y2 + base_row;
        bdst = g_refs_bf + (size_t)base_row * D;
    } else {
        int r = base_row - NREF;
        if (r >= NQ) return;
        srcp = feat + (size_t)r * D; dst = g_x2 + r;
        bdst = g_feat_bf + (size_t)r * D;
    }
    const float4* s4 = (const float4*)srcp;
    float4 v[4];
    v[0] = s4[l]; v[1] = s4[l + 32]; v[2] = s4[l + 64]; v[3] = s4[l + 96];
    float s[4];
    #pragma unroll
    for (int i = 0; i < 4; ++i) {
        s[i] = v[i].x * v[i].x + v[i].y * v[i].y + v[i].z * v[i].z + v[i].w * v[i].w;
        __nv_bfloat162 p0 = __floats2bfloat162_rn(v[i].x, v[i].y);
        __nv_bfloat162 p1 = __floats2bfloat162_rn(v[i].z, v[i].w);
        uint2 packed;
        packed.x = *(uint32_t*)&p0;
        packed.y = *(uint32_t*)&p1;
        ((uint2*)(bdst + (size_t)i * D))[l] = packed;
    }
    #pragma unroll
    for (int o = 16; o; o >>= 1) {
        #pragma unroll
        for (int i = 0; i < 4; ++i) s[i] += __shfl_xor_sync(0xffffffffu, s[i], o);
    }
    if (l == 0) *(float4*)dst = make_float4(s[0], s[1], s[2], s[3]);
}

// ---------------------------------------------------------------- kernel 2: bf16 mma main
__global__ void __launch_bounds__(256, 1)
knn_main_kernel() {
    extern __shared__ __align__(16) unsigned char smem[];
    const uint32_t sAu  = smem_u32(smem);
    const uint32_t sB0u = sAu + TILEB;
    const uint32_t sB1u = sAu + 2 * TILEB;
    float* sD = (float*)(smem + 3 * TILEB);

    const int t  = threadIdx.x;
    const int w  = t >> 5, l = t & 31;
    const int wm = w >> 2, wn = w & 3;     // warp grid 2(m) x 4(n)
    const int gr = l >> 2, lc = l & 3;     // C-fragment lane coords
    const int phase = l >> 3, pi = l & 7;  // ldmatrix lane roles

    const int split = blockIdx.x;
    const int qbase = blockIdx.y * 128;
    const int sbase = split * NCH * BN;

    // per-lane ldmatrix base addresses
    // A x4: matrices [m0-7,k0-7][m8-15,k0-7][m0-7,k8-15][m8-15,k8-15]
    uint32_t aoff[4];
    {
        const int prow = (phase & 1) * 8 + pi;
        const int pkof = (phase >> 1) * 16;
        #pragma unroll
        for (int it = 0; it < 4; ++it)
            aoff[it] = sAu + (uint32_t)((wm * 64 + it * 16 + prow) * ROWB + pkof);
    }
    // B x4: matrices [n0-7,k0-7][n0-7,k8-15][n8-15,k0-7][n8-15,k8-15]
    uint32_t boff[2];
    {
        const int bn  = (phase >> 1) * 8 + pi;
        const int bkof = (phase & 1) * 16;
        #pragma unroll
        for (int g = 0; g < 2; ++g)
            boff[g] = (uint32_t)((wn * 32 + g * 16 + bn) * ROWB + bkof);
    }

    // prologue: A tile + chunk0 B tile
    load_tile_bf(sAu, g_feat_bf, qbase, qbase + 128);
    load_tile_bf(sB0u, g_refs_bf, sbase, NREF);
    CPA_COMMIT();

    float tk[KNN];
    #pragma unroll
    for (int j = 0; j < KNN; ++j) tk[j] = BIGF;

    for (int ch = 0; ch < NCH; ++ch) {
        const int cbase = sbase + ch * BN;
        const uint32_t Bcur = (ch & 1) ? sB1u : sB0u;

        // y2 for this thread's 8 output columns
        float y2r[8];
        #pragma unroll
        for (int j = 0; j < 4; ++j) {
            const int c0 = wn * 32 + j * 8 + 2 * lc;
            const int n0 = cbase + c0;
            y2r[2 * j]     = (n0     < NREF) ? g_y2[n0]     : BIGF;
            y2r[2 * j + 1] = (n0 + 1 < NREF) ? g_y2[n0 + 1] : BIGF;
        }

        CPA_WAIT0();
        __syncthreads();      // B(ch) resident; selection of ch-1 done with sD

        // prefetch next chunk's B into the other buffer (overlaps whole k-loop)
        if (ch + 1 < NCH)
            load_tile_bf((ch & 1) ? sB0u : sB1u, g_refs_bf, cbase + BN, NREF);
        CPA_COMMIT();

        float acc[4][4][4];
        #pragma unroll
        for (int i = 0; i < 4; ++i)
            #pragma unroll
            for (int j = 0; j < 4; ++j)
                #pragma unroll
                for (int e = 0; e < 4; ++e) acc[i][j][e] = 0.f;

        #pragma unroll
        for (int ks = 0; ks < 8; ++ks) {
            const uint32_t kb = ks * 32;   // 16 bf16 = 32 B per k-step
            uint32_t af[4][4], bf4[2][4];
            #pragma unroll
            for (int it = 0; it < 4; ++it) LDSM4(af[it], aoff[it] + kb);
            #pragma unroll
            for (int g = 0; g < 2; ++g)    LDSM4(bf4[g], Bcur + boff[g] + kb);
            #pragma unroll
            for (int it = 0; it < 4; ++it)
                #pragma unroll
                for (int g = 0; g < 2; ++g)
                    #pragma unroll
                    for (int h = 0; h < 2; ++h)
                        mma_bf16(acc[it][2 * g + h], af[it],
                                 bf4[g][2 * h], bf4[g][2 * h + 1]);
        }

        // epilogue: d^2' = y^2 - 2*dot -> sD
        #pragma unroll
        for (int i = 0; i < 4; ++i) {
            const int r0 = wm * 64 + i * 16 + gr;
            #pragma unroll
            for (int j = 0; j < 4; ++j) {
                const int c0 = wn * 32 + j * 8 + 2 * lc;
                sD[r0 * SDS + c0]           = fmaf(-2.f, acc[i][j][0], y2r[2 * j]);
                sD[r0 * SDS + c0 + 1]       = fmaf(-2.f, acc[i][j][1], y2r[2 * j + 1]);
                sD[(r0 + 8) * SDS + c0]     = fmaf(-2.f, acc[i][j][2], y2r[2 * j]);
                sD[(r0 + 8) * SDS + c0 + 1] = fmaf(-2.f, acc[i][j][3], y2r[2 * j + 1]);
            }
        }
        __syncthreads();

        // selection: 2 threads per query, 64 columns each
        {
            const int q = t & 127, s = t >> 7;
            const float* rowp = sD + q * SDS + s * 64;
            #pragma unroll 4
            for (int c = 0; c < 64; ++c) topk_insert(tk, rowp[c]);
        }
    }

    // merge the two selectors' sorted lists per query via sD staging
    __syncthreads();
    {
        const int q = t & 127, s = t >> 7;
        #pragma unroll
        for (int j = 0; j < KNN; ++j) sD[(s * KNN + j) * 128 + q] = tk[j];
    }
    __syncthreads();
    if (t < 128) {
        float out[KNN];
        int ia = 0, ib = 0;
        #pragma unroll
        for (int o = 0; o < KNN; ++o) {
            const float va = sD[ia * 128 + t];
            const float vb = sD[(KNN + ib) * 128 + t];
            const bool ta = va <= vb;
            out[o] = ta ? va : vb;
            ia += ta;
            ib += !ta;
        }
        const int qg = qbase + t;
        #pragma unroll
        for (int o = 0; o < KNN; ++o)
            g_cand[(split * KNN + o) * NQ + qg] = out[o];
    }
}

// ---------------------------------------------------------------- kernel 3: finalize
__global__ void finalize_kernel(float* __restrict__ out) {
    const int q = blockIdx.x * blockDim.x + threadIdx.x;
    if (q >= NQ) return;
    float tk[KNN];
    #pragma unroll
    for (int j = 0; j < KNN; ++j) tk[j] = BIGF;
    #pragma unroll 4
    for (int i = 0; i < NSPLIT * KNN; ++i)
        topk_insert(tk, g_cand[i * NQ + q]);
    const float x2 = g_x2[q];
    float s = 0.f;
    #pragma unroll
    for (int j = 0; j < KNN; ++j) s += sqrtf(fmaxf(x2 + tk[j], 0.f));
    out[q] = -s * (1.0f / KNN);
}

// ---------------------------------------------------------------- launch
extern "C" void kernel_launch(void* const* d_in, const int* in_sizes, int n_in,
                              void* d_out, int out_size) {
    const float* feat = (const float*)d_in[0];
    const float* refs = (const float*)d_in[1];
    if (n_in >= 2 && in_sizes[0] > in_sizes[1]) {
        feat = (const float*)d_in[1];
        refs = (const float*)d_in[0];
    }

    cudaFuncSetAttribute(knn_main_kernel,
                         cudaFuncAttributeMaxDynamicSharedMemorySize, SMEM_BYTES);

    norms_kernel<<<(NREF + NQ) / 32, 256>>>(feat, refs);

    dim3 grid(NSPLIT, NQ / 128);
    knn_main_kernel<<<grid, 256, SMEM_BYTES>>>();

    finalize_kernel<<<2, 256>>>((float*)d_out);
}